// round 2
// baseline (speedup 1.0000x reference)
#include <cuda_runtime.h>
#include <math.h>

// ---------------------------------------------------------------------------
// Qwen2MoeAttention: B=2, S=2048, H=2048, NH=16, NKV=4, HD=128, theta=1e6
// Pipeline: QKV GEMM (+bias) -> RoPE(q,k) -> GQA causal flash attention -> Wo GEMM
// All compute-heavy inner loops use packed fma.rn.f32x2 (2x fp32 FFMA rate).
// Packed f32x2 carried in unsigned long long (inline-asm "l" constraint).
// ---------------------------------------------------------------------------

#define QSTR 130   // Q/K smem row stride (floats): even (f32x2 aligned), bank-stride 2
#define VSTR 132   // V smem row stride
#define PSTR 65    // probs smem row stride (odd -> conflict-free column reads)

typedef unsigned long long u64;

static __device__ float g_qkv[4096 * 3072];   // [token][3072] : q(2048)|k(512)|v(512)
static __device__ float g_attn[4096 * 2048];  // [token][NH*HD]

__device__ __forceinline__ u64 ffma2(u64 a, u64 b, u64 c) {
    u64 d;
    asm("fma.rn.f32x2 %0,%1,%2,%3;" : "=l"(d) : "l"(a), "l"(b), "l"(c));
    return d;
}
__device__ __forceinline__ u64 fmul2(u64 a, u64 b) {
    u64 d;
    asm("mul.rn.f32x2 %0,%1,%2;" : "=l"(d) : "l"(a), "l"(b));
    return d;
}
__device__ __forceinline__ u64 splat2(float x) {
    u64 d;
    asm("mov.b64 %0,{%1,%1};" : "=l"(d) : "r"(__float_as_uint(x)));
    return d;
}
__device__ __forceinline__ float2 unpack2(u64 a) {
    unsigned lo, hi;
    asm("mov.b64 {%0,%1},%2;" : "=r"(lo), "=r"(hi) : "l"(a));
    return make_float2(__uint_as_float(lo), __uint_as_float(hi));
}

// ---------------------------------------------------------------------------
// SGEMM: C[M,N] = A[M,K] @ B[K,N] (+ bias). 128x128 block, 8x8/thread, f32x2.
// ---------------------------------------------------------------------------
__global__ __launch_bounds__(256) void sgemm_bias_kernel(
    const float* __restrict__ A, const float* __restrict__ Bm,
    const float* __restrict__ bias, float* __restrict__ C,
    int M, int N, int K)
{
    __shared__ float As[8][128];   // transposed A tile: As[k][m]
    __shared__ float Bs[8][128];   // Bs[k][n]

    const int tid = threadIdx.x;
    const int tx = tid & 15;       // n-dir
    const int ty = tid >> 4;       // m-dir
    const int bm = blockIdx.y, bn = blockIdx.x;

    const int arow = tid >> 1;          // 0..127
    const int acol = (tid & 1) << 2;    // 0 or 4
    const int brow = tid >> 5;          // 0..7
    const int bcol = (tid & 31) << 2;   // 0..124

    const float* Aptr = A + (size_t)(bm * 128 + arow) * K + acol;
    const float* Bptr = Bm + (size_t)brow * N + bn * 128 + bcol;

    u64 c2[4][8];
#pragma unroll
    for (int i = 0; i < 4; i++)
#pragma unroll
        for (int j = 0; j < 8; j++) c2[i][j] = 0ull;

    float4 aR = *(const float4*)Aptr;
    float4 bR = *(const float4*)Bptr;
    const int ntiles = K >> 3;

    As[acol + 0][arow] = aR.x; As[acol + 1][arow] = aR.y;
    As[acol + 2][arow] = aR.z; As[acol + 3][arow] = aR.w;
    *(float4*)&Bs[brow][bcol] = bR;
    __syncthreads();

    for (int t = 1; t <= ntiles; t++) {
        if (t < ntiles) {
            aR = *(const float4*)(Aptr + t * 8);
            bR = *(const float4*)(Bptr + (size_t)t * 8 * N);
        }
#pragma unroll
        for (int kk = 0; kk < 8; kk++) {
            ulonglong2 a01 = *(const ulonglong2*)&As[kk][ty << 3];
            ulonglong2 a23 = *(const ulonglong2*)(&As[kk][ty << 3] + 4);
            float4 b03 = *(const float4*)&Bs[kk][tx << 3];
            float4 b47 = *(const float4*)(&Bs[kk][tx << 3] + 4);
            u64 a2[4] = {a01.x, a01.y, a23.x, a23.y};
            u64 b2[8] = {splat2(b03.x), splat2(b03.y), splat2(b03.z), splat2(b03.w),
                         splat2(b47.x), splat2(b47.y), splat2(b47.z), splat2(b47.w)};
#pragma unroll
            for (int i = 0; i < 4; i++)
#pragma unroll
                for (int j = 0; j < 8; j++) c2[i][j] = ffma2(a2[i], b2[j], c2[i][j]);
        }
        __syncthreads();
        if (t < ntiles) {
            As[acol + 0][arow] = aR.x; As[acol + 1][arow] = aR.y;
            As[acol + 2][arow] = aR.z; As[acol + 3][arow] = aR.w;
            *(float4*)&Bs[brow][bcol] = bR;
            __syncthreads();
        }
    }

    const int col0 = bn * 128 + (tx << 3);
    float bl[8];
#pragma unroll
    for (int j = 0; j < 8; j++) bl[j] = bias ? bias[col0 + j] : 0.0f;

#pragma unroll
    for (int i2 = 0; i2 < 4; i2++) {
        float lo[8], hi[8];
#pragma unroll
        for (int j = 0; j < 8; j++) {
            float2 v = unpack2(c2[i2][j]);
            lo[j] = v.x + bl[j];
            hi[j] = v.y + bl[j];
        }
        size_t r0 = (size_t)(bm * 128 + (ty << 3) + (i2 << 1));
        float* Crow = C + r0 * N + col0;
        *(float4*)Crow = make_float4(lo[0], lo[1], lo[2], lo[3]);
        *(float4*)(Crow + 4) = make_float4(lo[4], lo[5], lo[6], lo[7]);
        float* Crow2 = Crow + N;
        *(float4*)Crow2 = make_float4(hi[0], hi[1], hi[2], hi[3]);
        *(float4*)(Crow2 + 4) = make_float4(hi[4], hi[5], hi[6], hi[7]);
    }
}

// ---------------------------------------------------------------------------
// RoPE in-place on q (16 heads) and k (4 heads) inside g_qkv.
// grid: (4096 tokens, 20 heads), 64 threads = HD/2 pairs.
// ---------------------------------------------------------------------------
__global__ void rope_kernel(const int* __restrict__ positions, float* __restrict__ qkv) {
    const int token = blockIdx.x;
    const int hh = blockIdx.y;     // 0..15 -> q heads, 16..19 -> k heads
    const int t = threadIdx.x;     // 0..63
    float* base = qkv + (size_t)token * 3072 +
                  (hh < 16 ? hh * 128 : 2048 + (hh - 16) * 128);
    const float pos = (float)positions[token];
    const float e = (float)(2 * t) * (1.0f / 128.0f);
    const float inv = 1.0f / powf(1000000.0f, e);
    const float ang = pos * inv;
    float sv, cv;
    sincosf(ang, &sv, &cv);
    const float x1 = base[t];
    const float x2 = base[t + 64];
    base[t]      = x1 * cv - x2 * sv;
    base[t + 64] = x2 * cv + x1 * sv;
}

// ---------------------------------------------------------------------------
// Flash attention: 64 queries x 64 keys tiles, online softmax, f32x2 math.
// grid: (S/64=32, NH=16, B=2), 256 threads (16x16), dynamic smem 84480 B.
// Thread (ti,tj): scores for i=ti+16r, j=tj+16c; PV output d=2*tj+32*c (+1).
// ---------------------------------------------------------------------------
__global__ __launch_bounds__(256) void attn_kernel(
    const float* __restrict__ qkv, float* __restrict__ outp)
{
    extern __shared__ float sm[];
    float* Qs = sm;                    // 64*130
    float* Ks = Qs + 64 * QSTR;        // union: K tile (64*130) / V tile (64*132)
    float* Ps = Ks + 8448;             // 64*65 probs (Ps[i*65+j])
    float* mArr = Ps + 64 * PSTR;      // running max [64]
    float* lArr = mArr + 64;           // running sum [64]
    float* aArr = lArr + 64;           // per-chunk alpha [64]

    const int tid = threadIdx.x;
    const int ti = tid >> 4;
    const int tj = tid & 15;
    const int qt = blockIdx.x;
    const int h = blockIdx.y;
    const int b = blockIdx.z;
    const int q0 = qt * 64;
    const int tb = b * 2048;
    const int kvh = h >> 2;

    const float* Qg = qkv + (size_t)(tb + q0) * 3072 + h * 128;
    const float* Kg = qkv + (size_t)tb * 3072 + 2048 + kvh * 128;
    const float* Vg = qkv + (size_t)tb * 3072 + 2560 + kvh * 128;
    const float scale = 0.08838834764831845f;  // 1/sqrt(128)

    for (int idx = tid; idx < 64 * 128; idx += 256) {
        int i = idx >> 7, d = idx & 127;
        Qs[i * QSTR + d] = Qg[(size_t)i * 3072 + d] * scale;
    }
    if (tid < 64) { mArr[tid] = -3.0e38f; lArr[tid] = 0.0f; }

    u64 acc2[4][4];
#pragma unroll
    for (int r = 0; r < 4; r++)
#pragma unroll
        for (int c = 0; c < 4; c++) acc2[r][c] = 0ull;
    __syncthreads();

    const int nck = qt + 1;
    for (int ck = 0; ck < nck; ck++) {
        const int k0 = ck * 64;
        // load K tile
        for (int idx = tid; idx < 64 * 128; idx += 256) {
            int j = idx >> 7, d = idx & 127;
            Ks[j * QSTR + d] = Kg[(size_t)(k0 + j) * 3072 + d];
        }
        __syncthreads();

        // scores: s(i,j) = sum_d Qs[i][d]*Ks[j][d], packed over d-pairs
        u64 s2[4][4];
#pragma unroll
        for (int r = 0; r < 4; r++)
#pragma unroll
            for (int c = 0; c < 4; c++) s2[r][c] = 0ull;

#pragma unroll 8
        for (int d2 = 0; d2 < 64; d2++) {
            u64 q2[4], k2[4];
#pragma unroll
            for (int r = 0; r < 4; r++)
                q2[r] = *(const u64*)&Qs[(ti + 16 * r) * QSTR + 2 * d2];
#pragma unroll
            for (int c = 0; c < 4; c++)
                k2[c] = *(const u64*)&Ks[(tj + 16 * c) * QSTR + 2 * d2];
#pragma unroll
            for (int r = 0; r < 4; r++)
#pragma unroll
                for (int c = 0; c < 4; c++) s2[r][c] = ffma2(q2[r], k2[c], s2[r][c]);
        }

        const bool diag = (ck == qt);
#pragma unroll
        for (int r = 0; r < 4; r++)
#pragma unroll
            for (int c = 0; c < 4; c++) {
                float2 v = unpack2(s2[r][c]);
                float s = v.x + v.y;
                int i = ti + 16 * r, j = tj + 16 * c;
                if (diag && j > i) s = -3.0e38f;
                Ps[i * PSTR + j] = s;
            }
        __syncthreads();

        // online softmax row pass (one thread per query row)
        if (tid < 64) {
            const int i = tid;
            float mold = mArr[i];
            float mc = mold;
            for (int j = 0; j < 64; j++) mc = fmaxf(mc, Ps[i * PSTR + j]);
            float alpha = __expf(mold - mc);
            float lsum = 0.0f;
            for (int j = 0; j < 64; j++) {
                float p = __expf(Ps[i * PSTR + j] - mc);
                Ps[i * PSTR + j] = p;
                lsum += p;
            }
            mArr[i] = mc;
            lArr[i] = lArr[i] * alpha + lsum;
            aArr[i] = alpha;
        }
        __syncthreads();

        // rescale accumulators, then load V into the K/V union buffer
        u64 al2[4];
#pragma unroll
        for (int r = 0; r < 4; r++) al2[r] = splat2(aArr[ti + 16 * r]);
#pragma unroll
        for (int r = 0; r < 4; r++)
#pragma unroll
            for (int c = 0; c < 4; c++) acc2[r][c] = fmul2(acc2[r][c], al2[r]);

        for (int idx = tid; idx < 64 * 128; idx += 256) {
            int j = idx >> 7, d = idx & 127;
            Ks[j * VSTR + d] = Vg[(size_t)(k0 + j) * 3072 + d];
        }
        __syncthreads();

        // PV: o(i,d) += P(i,j)*V(j,d), packed over d-pairs
#pragma unroll 4
        for (int j = 0; j < 64; j++) {
            u64 p2[4];
#pragma unroll
            for (int r = 0; r < 4; r++) p2[r] = splat2(Ps[(ti + 16 * r) * PSTR + j]);
            u64 v2[4];
#pragma unroll
            for (int c = 0; c < 4; c++)
                v2[c] = *(const u64*)&Ks[j * VSTR + 2 * tj + 32 * c];
#pragma unroll
            for (int r = 0; r < 4; r++)
#pragma unroll
                for (int c = 0; c < 4; c++) acc2[r][c] = ffma2(p2[r], v2[c], acc2[r][c]);
        }
        __syncthreads();
    }

    // epilogue: divide by l, store [token][h*128+d]
    float* Og = outp + (size_t)(tb + q0) * 2048 + h * 128;
#pragma unroll
    for (int r = 0; r < 4; r++) {
        int i = ti + 16 * r;
        float inv = 1.0f / lArr[i];
#pragma unroll
        for (int c = 0; c < 4; c++) {
            float2 v = unpack2(acc2[r][c]);
            int d = 2 * tj + 32 * c;
            float2 o = make_float2(v.x * inv, v.y * inv);
            *(float2*)&Og[(size_t)i * 2048 + d] = o;
        }
    }
}

// ---------------------------------------------------------------------------
extern "C" void kernel_launch(void* const* d_in, const int* in_sizes, int n_in,
                              void* d_out, int out_size)
{
    const int* positions = (const int*)d_in[0];
    const float* hidden  = (const float*)d_in[1];
    const float* Wqkv    = (const float*)d_in[2];
    const float* bqkv    = (const float*)d_in[3];
    const float* Wo      = (const float*)d_in[4];
    float* out = (float*)d_out;

    float *qkv, *attn;
    cudaGetSymbolAddress((void**)&qkv, g_qkv);
    cudaGetSymbolAddress((void**)&attn, g_attn);

    // 1) QKV projection + bias: [4096,2048] @ [2048,3072]
    sgemm_bias_kernel<<<dim3(3072 / 128, 4096 / 128), 256>>>(
        hidden, Wqkv, bqkv, qkv, 4096, 3072, 2048);

    // 2) RoPE on q and k heads
    rope_kernel<<<dim3(4096, 20), 64>>>(positions, qkv);

    // 3) causal GQA flash attention
    const size_t ATTN_SMEM = (size_t)(64 * QSTR + 8448 + 64 * PSTR + 192) * sizeof(float); // 84480
    cudaFuncSetAttribute(attn_kernel, cudaFuncAttributeMaxDynamicSharedMemorySize,
                         (int)ATTN_SMEM);
    attn_kernel<<<dim3(32, 16, 2), 256, ATTN_SMEM>>>(qkv, attn);

    // 4) output projection: [4096,2048] @ [2048,2048]
    sgemm_bias_kernel<<<dim3(2048 / 128, 4096 / 128), 256>>>(
        attn, Wo, nullptr, out, 4096, 2048, 2048);
}